// round 15
// baseline (speedup 1.0000x reference)
#include <cuda_runtime.h>

#define SCALE 0.17677669529663687f
#define NTHR  512

// u32-word smem offsets — per-CTA smem = 195,584 B (1 CTA/SM, 16 warps)
// XHH [0,7616)      : hi plane, 112 rows x 68 words (2 windows @ 56-row slabs)
// XHL [7616,15232)  : lo plane
// KH  [15232,30464) : uint2 112x68 — B operand for QK (pad rows zeroed)
// VT  [30464,48896) : uint2 2x128x36 — B operand for AV
// q then OV overlay the XH planes
#define SM_WORDS 48896

__device__ uint4  gW4[64 * 8 * 8 * 4];      // fragment-major pre-split weights
__device__ float2 gBM[64 * 4 * 7 * 49 * 4]; // bias+mask: [wm][h][jb][li][t]

__device__ __forceinline__ unsigned pack_bf(float x0, float x1) {
    unsigned r;
    asm("cvt.rn.bf16x2.f32 %0, %1, %2;" : "=r"(r) : "f"(x1), "f"(x0));
    return r;
}
__device__ __forceinline__ uint2 split_pack(float x0, float x1) {
    unsigned h = pack_bf(x0, x1);
    float h0 = __uint_as_float(h << 16);
    float h1 = __uint_as_float(h & 0xffff0000u);
    unsigned l = pack_bf(x0 - h0, x1 - h1);
    return make_uint2(h, l);
}
__device__ __forceinline__ void mmabf(float* d, const unsigned* a, const unsigned* b) {
    asm volatile("mma.sync.aligned.m16n8k16.row.col.f32.bf16.bf16.f32 "
        "{%0,%1,%2,%3},{%4,%5,%6,%7},{%8,%9},{%0,%1,%2,%3};"
        : "+f"(d[0]), "+f"(d[1]), "+f"(d[2]), "+f"(d[3])
        : "r"(a[0]), "r"(a[1]), "r"(a[2]), "r"(a[3]), "r"(b[0]), "r"(b[1]));
}
__device__ __forceinline__ void mma3(float* d, const unsigned ah[4], const unsigned al[4],
                                     uint2 b0, uint2 b1) {
    unsigned bh[2] = {b0.x, b1.x};
    unsigned bl[2] = {b0.y, b1.y};
    mmabf(d, ah, bl);
    mmabf(d, al, bh);
    mmabf(d, ah, bh);
}
__device__ __forceinline__ void ldsm4(unsigned r[4], unsigned a) {
    asm volatile("ldmatrix.sync.aligned.m8n8.x4.shared.b16 {%0,%1,%2,%3}, [%4];"
        : "=r"(r[0]), "=r"(r[1]), "=r"(r[2]), "=r"(r[3]) : "r"(a));
}

// Dense stage: warp computes 16 rows x 64 cols, K=128. One LDSM pair feeds 8 n-blocks.
__device__ __forceinline__ void mma_dense8(unsigned hb, unsigned lb,
                                           const uint4* __restrict__ gBw,
                                           float d[8][4], int lane)
{
    #pragma unroll
    for (int kb = 0; kb < 8; ++kb) {
        unsigned ah[4], al[4];
        ldsm4(ah, hb + kb * 32);
        ldsm4(al, lb + kb * 32);
        #pragma unroll
        for (int nb = 0; nb < 8; ++nb) {
            uint4 f = gBw[nb * 256 + kb * 32 + lane];   // 512B coalesced
            mma3(d[nb], ah, al, make_uint2(f.x, f.y), make_uint2(f.z, f.w));
        }
    }
}

// combined prep: blocks [0,64) build gW4, blocks [64,..) build gBM
__global__ void prep_all(const float* __restrict__ qkv_w,
                         const float* __restrict__ proj_w,
                         const float* __restrict__ attn_mask,
                         const float* __restrict__ bias_table,
                         const int*   __restrict__ rel_idx)
{
    if (blockIdx.x < 64) {
        int idx = blockIdx.x * 256 + threadIdx.x;       // 0..16383
        int t    = idx & 3;
        int g    = (idx >> 2) & 7;
        int kb   = (idx >> 5) & 7;
        int cblk = idx >> 8;
        int col  = cblk * 8 + g;
        const float* src = (col < 384) ? (qkv_w + (size_t)col * 128)
                                       : (proj_w + (size_t)(col - 384) * 128);
        int w0 = kb * 8 + t, w1 = w0 + 4;
        uint2 p0 = split_pack(src[2 * w0], src[2 * w0 + 1]);
        uint2 p1 = split_pack(src[2 * w1], src[2 * w1 + 1]);
        gW4[idx] = make_uint4(p0.x, p0.y, p1.x, p1.y);
    } else {
        int idx = (blockIdx.x - 64) * 256 + threadIdx.x;
        if (idx >= 64 * 4 * 7 * 49 * 4) return;
        int t  = idx & 3;
        int q  = idx >> 2;
        int li = q % 49;   q /= 49;
        int jb = q % 7;    q /= 7;
        int h  = q & 3;
        int wm = q >> 2;
        int j0 = jb * 8 + 2 * t;
        float v0 = -1e30f, v1 = -1e30f;
        if (j0 < 49)
            v0 = bias_table[rel_idx[li * 49 + j0] * 4 + h] + attn_mask[wm * 2401 + li * 49 + j0];
        if (j0 + 1 < 49)
            v1 = bias_table[rel_idx[li * 49 + j0 + 1] * 4 + h] + attn_mask[wm * 2401 + li * 49 + j0 + 1];
        gBM[idx] = make_float2(v0, v1);
    }
}

__global__ __launch_bounds__(NTHR, 1)
void wmsa_fused_kernel(const float* __restrict__ x,
                       const float* __restrict__ qkv_b,
                       const float* __restrict__ proj_b,
                       float* __restrict__ out)
{
    extern __shared__ unsigned sm32[];
    unsigned* XHH = sm32;                    // hi plane (x -> q -> ov)
    unsigned* XHL = sm32 + 7616;             // lo plane
    uint2*    KH  = (uint2*)(sm32 + 15232);
    uint2*    VT  = (uint2*)(sm32 + 30464);

    const int tid  = threadIdx.x;
    const int bx   = blockIdx.x;             // 0..2047 (two windows each)
    const int lane = tid & 31;
    const int wid  = tid >> 5;               // 0..15
    const int g    = lane >> 2;
    const int t    = lane & 3;

    // dense roles: 7 m-tiles x 2 col-halves = 14 tasks (warps 14,15 idle in dense)
    const int  mt   = wid >> 1;              // 0..7 (7 valid)
    const int  nh   = wid & 1;               // col half: cols nh*64 ..
    const bool dact = (wid < 14);
    const int  mtc  = min(mt, 6);

    const unsigned sb = (unsigned)__cvta_generic_to_shared(sm32);
    const unsigned rowoff = (lane & 15) * 272 + (lane >> 4) * 16;  // canonical LDSM addr
    const unsigned xhh_b = sb + rowoff;
    const unsigned xhl_b = sb + 7616u * 4 + rowoff;
    const unsigned dhb = xhh_b + mtc * 16 * 272;
    const unsigned dlb = xhl_b + mtc * 16 * 272;

    // ---------------- phase 0: load+split x (2 windows) ; zero VT + KH pads ----------------
    {
        const float2* xg = (const float2*)(x + (size_t)bx * 2 * 49 * 128);
        for (int idx = tid; idx < 2 * 49 * 64; idx += NTHR) {
            float2 v = xg[idx];
            uint2 p = split_pack(v.x, v.y);
            int win = idx / 3136, rem = idx - win * 3136;
            int o = (win * 56 + (rem >> 6)) * 68 + (rem & 63);
            XHH[o] = p.x;
            XHL[o] = p.y;
        }
        for (int idx = tid; idx < 2 * 128 * 36; idx += NTHR)
            VT[idx] = make_uint2(0, 0);
        for (int idx = tid; idx < 2 * 7 * 68; idx += NTHR) {   // KH rows 49..55, 105..111
            int win = idx / 476, rem = idx - win * 476;
            KH[(win * 56 + 49) * 68 + rem] = make_uint2(0, 0);
        }
    }
    __syncthreads();

    // ---------------- phase 1: K, V, Q dense stages ----------------
    {   // K (col blocks 16..31)
        float d[8][4] = {};
        if (dact) {
            mma_dense8(dhb, dlb, gW4 + (16 + nh * 8) * 256, d, lane);
            int r0 = mtc * 16 + g, r1 = r0 + 8;
            int i0 = (r0 >= 56) ? r0 - 56 : r0;
            int i1 = (r1 >= 56) ? r1 - 56 : r1;
            #pragma unroll
            for (int nb = 0; nb < 8; ++nb) {
                int c = nh * 64 + nb * 8 + 2 * t;
                float b0 = qkv_b[128 + c], b1 = qkv_b[129 + c];
                int wcol = c >> 1;
                if (i0 < 49) KH[r0 * 68 + wcol] = split_pack(d[nb][0] + b0, d[nb][1] + b1);
                if (i1 < 49) KH[r1 * 68 + wcol] = split_pack(d[nb][2] + b0, d[nb][3] + b1);
            }
        }
    }
    {   // V (col blocks 32..47) -> VT transposed via shfl pairing
        float d[8][4] = {};
        if (dact) {
            mma_dense8(dhb, dlb, gW4 + (32 + nh * 8) * 256, d, lane);
            #pragma unroll
            for (int nb = 0; nb < 8; ++nb) {
                int c = nh * 64 + nb * 8 + 2 * t;
                float b0 = qkv_b[256 + c], b1 = qkv_b[257 + c];
                #pragma unroll
                for (int rr = 0; rr < 2; ++rr) {
                    float vc  = d[nb][2 * rr]     + b0;
                    float vc1 = d[nb][2 * rr + 1] + b1;
                    float oc  = __shfl_xor_sync(0xffffffffu, vc, 4);
                    float oc1 = __shfl_xor_sync(0xffffffffu, vc1, 4);
                    int r = mtc * 16 + rr * 8 + g;
                    int wn = (r >= 56);
                    int il = r - 56 * wn;
                    if (!(g & 1) && il < 49) {
                        float e1 = (il + 1 < 49) ? oc  : 0.f;
                        float f1 = (il + 1 < 49) ? oc1 : 0.f;
                        int u = il >> 1;
                        VT[(wn * 128 + c)     * 36 + u] = split_pack(vc,  e1);
                        VT[(wn * 128 + c + 1) * 36 + u] = split_pack(vc1, f1);
                    }
                }
            }
        }
    }
    {   // Q (col blocks 0..15): compute, sync, overwrite XH planes
        float d[8][4] = {};
        if (dact) mma_dense8(dhb, dlb, gW4 + nh * 8 * 256, d, lane);
        __syncthreads();                      // all XH reads done
        if (dact) {
            int r0 = mtc * 16 + g, r1 = r0 + 8;
            int i0 = (r0 >= 56) ? r0 - 56 : r0;
            int i1 = (r1 >= 56) ? r1 - 56 : r1;
            #pragma unroll
            for (int nb = 0; nb < 8; ++nb) {
                int c = nh * 64 + nb * 8 + 2 * t;
                float b0 = qkv_b[c], b1 = qkv_b[c + 1];
                int wcol = c >> 1;
                if (i0 < 49) {
                    uint2 p = split_pack((d[nb][0] + b0) * SCALE, (d[nb][1] + b1) * SCALE);
                    XHH[r0 * 68 + wcol] = p.x;
                    XHL[r0 * 68 + wcol] = p.y;
                }
                if (i1 < 49) {
                    uint2 p = split_pack((d[nb][2] + b0) * SCALE, (d[nb][3] + b1) * SCALE);
                    XHH[r1 * 68 + wcol] = p.x;
                    XHL[r1 * 68 + wcol] = p.y;
                }
            }
        }
    }
    __syncthreads();

    // ------- phases 2-4 fused: per-task QK -> softmax -> AV -> inline OV store -------
    // 32 tasks = 2 windows x 4 heads x 4 q-tiles; OV overlays q planes (row/word disjoint).
    #pragma unroll
    for (int it = 0; it < 2; ++it) {
        int task = wid + 16 * it;             // 0..31
        int wn = task >> 4, rem = task & 15;
        int h = rem >> 2, qt = rem & 3;
        int rowg = wn * 56 + qt * 16;         // global base row

        // --- QK^T (A = q rows via LDSM, B = KH) ---
        float dq[7][4];
        #pragma unroll
        for (int jb = 0; jb < 7; ++jb)
            #pragma unroll
            for (int e = 0; e < 4; ++e) dq[jb][e] = 0.f;
        #pragma unroll
        for (int kb2 = 0; kb2 < 2; ++kb2) {
            int kb = 2 * h + kb2;
            unsigned ah[4], al[4];
            ldsm4(ah, xhh_b + rowg * 272 + kb * 32);
            ldsm4(al, xhl_b + rowg * 272 + kb * 32);
            int kw = kb * 8 + t;
            #pragma unroll
            for (int jb = 0; jb < 7; ++jb) {
                int kr = wn * 56 + jb * 8 + g;
                mma3(dq[jb], ah, al, KH[kr * 68 + kw], KH[kr * 68 + kw + 4]);
            }
        }

        // --- bias+mask + softmax -> packed A fragments (regs) ---
        uint2 pa[7], pb[7];
        const float2* bmh = gBM + ((size_t)((2 * bx + wn) & 63) * 4 + h) * (7 * 49 * 4);
        #pragma unroll
        for (int rr = 0; rr < 2; ++rr) {
            int li = qt * 16 + rr * 8 + g;
            int lic = min(li, 48);
            float sv[14];
            float mx = -INFINITY;
            #pragma unroll
            for (int jb = 0; jb < 7; ++jb) {
                float2 bm = bmh[(jb * 49 + lic) * 4 + t];
                float v0 = dq[jb][rr * 2]     + bm.x;
                float v1 = dq[jb][rr * 2 + 1] + bm.y;
                sv[2 * jb]     = v0;
                sv[2 * jb + 1] = v1;
                mx = fmaxf(mx, fmaxf(v0, v1));
            }
            mx = fmaxf(mx, __shfl_xor_sync(0xffffffffu, mx, 1));
            mx = fmaxf(mx, __shfl_xor_sync(0xffffffffu, mx, 2));
            float sum = 0.f;
            #pragma unroll
            for (int n = 0; n < 14; ++n) { sv[n] = __expf(sv[n] - mx); sum += sv[n]; }
            sum += __shfl_xor_sync(0xffffffffu, sum, 1);
            sum += __shfl_xor_sync(0xffffffffu, sum, 2);
            float inv = 1.f / sum;
            uint2* dst = rr ? pb : pa;
            #pragma unroll
            for (int jb = 0; jb < 7; ++jb)
                dst[jb] = split_pack(sv[2 * jb] * inv, sv[2 * jb + 1] * inv);
        }

        // --- AV (A = packed probs from regs, B = VT) ---
        float dv[4][4] = {};
        #pragma unroll
        for (int kb = 0; kb < 4; ++kb) {
            const int jb0 = 2 * kb, jb1 = 2 * kb + 1;
            unsigned ah[4], al[4];
            ah[0] = pa[jb0].x;  al[0] = pa[jb0].y;
            ah[1] = pb[jb0].x;  al[1] = pb[jb0].y;
            if (jb1 < 7) {
                ah[2] = pa[jb1].x;  al[2] = pa[jb1].y;
                ah[3] = pb[jb1].x;  al[3] = pb[jb1].y;
            } else {
                ah[2] = 0; al[2] = 0; ah[3] = 0; al[3] = 0;
            }
            int kw = kb * 8 + t;
            #pragma unroll
            for (int nb = 0; nb < 4; ++nb) {
                int c = wn * 128 + 32 * h + nb * 8 + g;
                mma3(dv[nb], ah, al, VT[c * 36 + kw], VT[c * 36 + kw + 4]);
            }
        }

        // --- inline OV store into the q planes (rows/words disjoint across tasks) ---
        {
            int l0 = qt * 16 + g;
            #pragma unroll
            for (int nb = 0; nb < 4; ++nb) {
                int cw = 16 * h + nb * 4 + t;
                if (l0 < 49) {
                    uint2 p = split_pack(dv[nb][0], dv[nb][1]);
                    XHH[(rowg + g) * 68 + cw] = p.x;
                    XHL[(rowg + g) * 68 + cw] = p.y;
                }
                if (l0 + 8 < 49) {
                    uint2 p = split_pack(dv[nb][2], dv[nb][3]);
                    XHH[(rowg + g + 8) * 68 + cw] = p.x;
                    XHL[(rowg + g + 8) * 68 + cw] = p.y;
                }
            }
        }
    }
    __syncthreads();                          // all OV writes visible

    // ---------------- phase 5: proj GEMM (col blocks 48..63), A = OV in XH planes ----------------
    {
        float d[8][4] = {};
        if (dact) {
            mma_dense8(dhb, dlb, gW4 + (48 + nh * 8) * 256, d, lane);
            int r0 = mtc * 16 + g, r1 = r0 + 8;
            int wn0 = (r0 >= 56), wn1 = (r1 >= 56);
            int i0 = r0 - 56 * wn0, i1 = r1 - 56 * wn1;
            float* og0 = out + ((size_t)(2 * bx + wn0) * 49 + i0) * 128;
            float* og1 = out + ((size_t)(2 * bx + wn1) * 49 + i1) * 128;
            #pragma unroll
            for (int nb = 0; nb < 8; ++nb) {
                int c = nh * 64 + nb * 8 + 2 * t;
                float b0 = proj_b[c], b1 = proj_b[c + 1];
                if (i0 < 49)
                    *(float2*)(og0 + c) = make_float2(d[nb][0] + b0, d[nb][1] + b1);
                if (i1 < 49)
                    *(float2*)(og1 + c) = make_float2(d[nb][2] + b0, d[nb][3] + b1);
            }
        }
    }
}

extern "C" void kernel_launch(void* const* d_in, const int* in_sizes, int n_in,
                              void* d_out, int out_size)
{
    const float* x          = (const float*)d_in[0];
    const float* attn_mask  = (const float*)d_in[1];
    const float* qkv_w      = (const float*)d_in[2];
    const float* qkv_b      = (const float*)d_in[3];
    const float* proj_w     = (const float*)d_in[4];
    const float* proj_b     = (const float*)d_in[5];
    const float* bias_table = (const float*)d_in[6];
    const int*   rel_idx    = (const int*)d_in[7];
    float* out = (float*)d_out;

    const int bm_blocks = (64 * 4 * 7 * 49 * 4 + 255) / 256;   // 215
    prep_all<<<64 + bm_blocks, 256>>>(qkv_w, proj_w, attn_mask, bias_table, rel_idx);

    const int smem_bytes = SM_WORDS * 4;                       // 195,584 B -> 1 CTA/SM
    cudaFuncSetAttribute(wmsa_fused_kernel,
                         cudaFuncAttributeMaxDynamicSharedMemorySize, smem_bytes);

    const int n_windows = in_sizes[0] / (49 * 128);            // 4096
    wmsa_fused_kernel<<<n_windows / 2, NTHR, smem_bytes>>>(x, qkv_b, proj_b, out);
}

// round 16
// speedup vs baseline: 1.3203x; 1.3203x over previous
#include <cuda_runtime.h>

#define LOG2E 1.4426950408889634
#define S2    ((float)(0.17677669529663687 * LOG2E))   // qk scale folded with log2e
#define NTHR  256

// u32-word smem offsets — per-CTA smem = 97,792 B (2 CTAs/SM)
// XHH [0,3808)   : hi plane, 56 rows x 68 words (stride 272B, LDSM-clean)
// XHL [3808,7616): lo plane
// KH  [7616,15232): uint2 56x68 (hi,lo packed) — B operand for QK
// VT  [15232,24448): uint2 128x36 — B operand for AV
// OV planes overlay XH planes after attention
#define SM_U2 12224

__device__ uint4  gW4[64 * 8 * 8 * 4];       // fragment-major pre-split weights (Q cols pre-scaled by S2)
__device__ float2 gBM[64 * 4 * 7 * 64 * 4];  // (bias+mask)*log2e: [wm][h][jb][li(64)][t]

__device__ __forceinline__ unsigned pack_bf(float x0, float x1) {
    unsigned r;
    asm("cvt.rn.bf16x2.f32 %0, %1, %2;" : "=r"(r) : "f"(x1), "f"(x0));
    return r;
}
__device__ __forceinline__ uint2 split_pack(float x0, float x1) {
    unsigned h = pack_bf(x0, x1);
    float h0 = __uint_as_float(h << 16);
    float h1 = __uint_as_float(h & 0xffff0000u);
    unsigned l = pack_bf(x0 - h0, x1 - h1);
    return make_uint2(h, l);
}
__device__ __forceinline__ float ex2f(float x) {
    float r; asm("ex2.approx.ftz.f32 %0, %1;" : "=f"(r) : "f"(x)); return r;
}
__device__ __forceinline__ void mmabf(float* d, const unsigned* a, const unsigned* b) {
    asm volatile("mma.sync.aligned.m16n8k16.row.col.f32.bf16.bf16.f32 "
        "{%0,%1,%2,%3},{%4,%5,%6,%7},{%8,%9},{%0,%1,%2,%3};"
        : "+f"(d[0]), "+f"(d[1]), "+f"(d[2]), "+f"(d[3])
        : "r"(a[0]), "r"(a[1]), "r"(a[2]), "r"(a[3]), "r"(b[0]), "r"(b[1]));
}
__device__ __forceinline__ void mma3(float* d, const unsigned ah[4], const unsigned al[4],
                                     uint2 b0, uint2 b1) {
    unsigned bh[2] = {b0.x, b1.x};
    unsigned bl[2] = {b0.y, b1.y};
    mmabf(d, ah, bl);
    mmabf(d, al, bh);
    mmabf(d, ah, bh);
}
__device__ __forceinline__ void ldsm4(unsigned r[4], unsigned a) {
    asm volatile("ldmatrix.sync.aligned.m8n8.x4.shared.b16 {%0,%1,%2,%3}, [%4];"
        : "=r"(r[0]), "=r"(r[1]), "=r"(r[2]), "=r"(r[3]) : "r"(a));
}

// Dense stage: warp computes 32 rows (two 16-row subtiles) x 32 cols, K=128.
// d must be pre-initialized (bias-fold) by the caller.
__device__ __forceinline__ void mma_dense_ldsm(unsigned hb, unsigned lb,
                                               const uint4* __restrict__ gBw,
                                               float d[2][4][4], int lane)
{
    #pragma unroll
    for (int kb = 0; kb < 8; ++kb) {
        unsigned ah0[4], al0[4], ah1[4], al1[4];
        ldsm4(ah0, hb + kb * 32);
        ldsm4(al0, lb + kb * 32);
        ldsm4(ah1, hb + 4352 + kb * 32);     // +16 rows * 272B
        ldsm4(al1, lb + 4352 + kb * 32);
        #pragma unroll
        for (int nb = 0; nb < 4; ++nb) {
            uint4 f = gBw[nb * 256 + kb * 32 + lane];   // 512B coalesced
            uint2 b0 = make_uint2(f.x, f.y);
            uint2 b1 = make_uint2(f.z, f.w);
            mma3(d[0][nb], ah0, al0, b0, b1);
            mma3(d[1][nb], ah1, al1, b0, b1);
        }
    }
}

// combined prep: blocks [0,64) build gW4, blocks [64,..) build gBM
__global__ void prep_all(const float* __restrict__ qkv_w,
                         const float* __restrict__ proj_w,
                         const float* __restrict__ attn_mask,
                         const float* __restrict__ bias_table,
                         const int*   __restrict__ rel_idx)
{
    if (blockIdx.x < 64) {
        int idx = blockIdx.x * 256 + threadIdx.x;       // 0..16383
        int t    = idx & 3;
        int g    = (idx >> 2) & 7;
        int kb   = (idx >> 5) & 7;
        int cblk = idx >> 8;
        int col  = cblk * 8 + g;
        const float* src = (col < 384) ? (qkv_w + (size_t)col * 128)
                                       : (proj_w + (size_t)(col - 384) * 128);
        float s = (col < 128) ? S2 : 1.0f;              // fold qk-scale*log2e into Q weights
        int w0 = kb * 8 + t, w1 = w0 + 4;
        uint2 p0 = split_pack(src[2 * w0] * s, src[2 * w0 + 1] * s);
        uint2 p1 = split_pack(src[2 * w1] * s, src[2 * w1 + 1] * s);
        gW4[idx] = make_uint4(p0.x, p0.y, p1.x, p1.y);
    } else {
        int idx = (blockIdx.x - 64) * 256 + threadIdx.x;
        if (idx >= 64 * 4 * 7 * 64 * 4) return;
        int t  = idx & 3;
        int q  = idx >> 2;
        int li = q & 63;   q >>= 6;
        int jb = q % 7;    q /= 7;
        int h  = q & 3;
        int wm = q >> 2;
        int j0 = jb * 8 + 2 * t;
        float v0 = -1e30f, v1 = -1e30f;
        if (li < 49 && j0 < 49)
            v0 = (bias_table[rel_idx[li * 49 + j0] * 4 + h]
                  + attn_mask[wm * 2401 + li * 49 + j0]) * (float)LOG2E;
        if (li < 49 && j0 + 1 < 49)
            v1 = (bias_table[rel_idx[li * 49 + j0 + 1] * 4 + h]
                  + attn_mask[wm * 2401 + li * 49 + j0 + 1]) * (float)LOG2E;
        gBM[idx] = make_float2(v0, v1);
    }
}

__global__ __launch_bounds__(NTHR, 2)
void wmsa_fused_kernel(const float* __restrict__ x,
                       const float* __restrict__ qkv_b,
                       const float* __restrict__ proj_b,
                       float* __restrict__ out)
{
    extern __shared__ unsigned sm32[];
    unsigned* XHH = sm32;                    // hi plane (x -> q -> ov)
    unsigned* XHL = sm32 + 3808;             // lo plane
    uint2*    KH  = (uint2*)(sm32 + 7616);
    uint2*    VT  = (uint2*)(sm32 + 15232);

    const int tid  = threadIdx.x;
    const int bx   = blockIdx.x;
    const int lane = tid & 31;
    const int wid  = tid >> 5;               // 0..7
    const int g    = lane >> 2;
    const int t    = lane & 3;

    const int mt2   = wid >> 2;              // 0..1
    const int nh    = wid & 3;
    const int rbase = mt2 * 32;
    const int cb    = nh * 32;
    const uint4* gBq = gW4 + (cb >> 3) * 256;

    const unsigned sb = (unsigned)__cvta_generic_to_shared(sm32);
    const unsigned rowoff = (lane & 15) * 272 + (lane >> 4) * 16;  // canonical LDSM addr
    const unsigned xhh_b = sb + rowoff;
    const unsigned xhl_b = sb + 3808u * 4 + rowoff;

    // ---------------- phase 0: load+split x (planes) ; zero VT + KH pads ----------------
    {
        const float2* xg = (const float2*)(x + (size_t)bx * 49 * 128);
        for (int idx = tid; idx < 49 * 64; idx += NTHR) {
            float2 v = xg[idx];
            uint2 p = split_pack(v.x, v.y);
            int o = (idx >> 6) * 68 + (idx & 63);
            XHH[o] = p.x;
            XHL[o] = p.y;
        }
        for (int idx = tid; idx < 128 * 36; idx += NTHR)
            VT[idx] = make_uint2(0, 0);
        for (int idx = tid; idx < 7 * 68; idx += NTHR)      // KH rows 49..55 = 0
            KH[49 * 68 + idx] = make_uint2(0, 0);
    }
    __syncthreads();

    // ---------------- phase 1: K, V, Q (bias pre-folded into accumulator init) ----------------
    {   // K (col block 16)
        float d[2][4][4];
        #pragma unroll
        for (int nb = 0; nb < 4; ++nb) {
            int c = cb + nb * 8 + 2 * t;
            float b0 = qkv_b[128 + c], b1 = qkv_b[129 + c];
            #pragma unroll
            for (int sub = 0; sub < 2; ++sub) {
                d[sub][nb][0] = b0; d[sub][nb][1] = b1;
                d[sub][nb][2] = b0; d[sub][nb][3] = b1;
            }
        }
        mma_dense_ldsm(xhh_b + rbase * 272, xhl_b + rbase * 272, gBq + 16 * 256, d, lane);
        #pragma unroll
        for (int sub = 0; sub < 2; ++sub) {
            int r0 = rbase + sub * 16 + g, r1 = r0 + 8;
            #pragma unroll
            for (int nb = 0; nb < 4; ++nb) {
                int wcol = (cb + nb * 8 + 2 * t) >> 1;
                if (r0 < 49) KH[r0 * 68 + wcol] = split_pack(d[sub][nb][0], d[sub][nb][1]);
                if (r1 < 49) KH[r1 * 68 + wcol] = split_pack(d[sub][nb][2], d[sub][nb][3]);
            }
        }
    }
    {   // V (col block 32) -> VT transposed via shfl pairing
        float d[2][4][4];
        #pragma unroll
        for (int nb = 0; nb < 4; ++nb) {
            int c = cb + nb * 8 + 2 * t;
            float b0 = qkv_b[256 + c], b1 = qkv_b[257 + c];
            #pragma unroll
            for (int sub = 0; sub < 2; ++sub) {
                d[sub][nb][0] = b0; d[sub][nb][1] = b1;
                d[sub][nb][2] = b0; d[sub][nb][3] = b1;
            }
        }
        mma_dense_ldsm(xhh_b + rbase * 272, xhl_b + rbase * 272, gBq + 32 * 256, d, lane);
        #pragma unroll
        for (int sub = 0; sub < 2; ++sub) {
            #pragma unroll
            for (int nb = 0; nb < 4; ++nb) {
                int c = cb + nb * 8 + 2 * t;
                #pragma unroll
                for (int rr = 0; rr < 2; ++rr) {
                    float vc  = d[sub][nb][2 * rr];
                    float vc1 = d[sub][nb][2 * rr + 1];
                    float oc  = __shfl_xor_sync(0xffffffffu, vc, 4);
                    float oc1 = __shfl_xor_sync(0xffffffffu, vc1, 4);
                    int il = rbase + sub * 16 + rr * 8 + g;
                    if (!(g & 1) && il < 49) {
                        float e1 = (il + 1 < 49) ? oc  : 0.f;
                        float f1 = (il + 1 < 49) ? oc1 : 0.f;
                        int u = il >> 1;
                        VT[c * 36 + u]       = split_pack(vc,  e1);
                        VT[(c + 1) * 36 + u] = split_pack(vc1, f1);
                    }
                }
            }
        }
    }
    {   // Q (col block 0, weights pre-scaled by S2): compute, sync, overwrite XH planes
        float d[2][4][4];
        #pragma unroll
        for (int nb = 0; nb < 4; ++nb) {
            int c = cb + nb * 8 + 2 * t;
            float b0 = qkv_b[c] * S2, b1 = qkv_b[c + 1] * S2;
            #pragma unroll
            for (int sub = 0; sub < 2; ++sub) {
                d[sub][nb][0] = b0; d[sub][nb][1] = b1;
                d[sub][nb][2] = b0; d[sub][nb][3] = b1;
            }
        }
        mma_dense_ldsm(xhh_b + rbase * 272, xhl_b + rbase * 272, gBq, d, lane);
        __syncthreads();                      // all XH reads done
        #pragma unroll
        for (int sub = 0; sub < 2; ++sub) {
            int r0 = rbase + sub * 16 + g, r1 = r0 + 8;
            #pragma unroll
            for (int nb = 0; nb < 4; ++nb) {
                int wcol = (cb + nb * 8 + 2 * t) >> 1;
                if (r0 < 49) {
                    uint2 p = split_pack(d[sub][nb][0], d[sub][nb][1]);
                    XHH[r0 * 68 + wcol] = p.x;
                    XHL[r0 * 68 + wcol] = p.y;
                }
                if (r1 < 49) {
                    uint2 p = split_pack(d[sub][nb][2], d[sub][nb][3]);
                    XHH[r1 * 68 + wcol] = p.x;
                    XHL[r1 * 68 + wcol] = p.y;
                }
            }
        }
    }
    __syncthreads();

    // ------- phases 2-4 fused: per-task QK(init=bias+mask) -> exp2 softmax -> AV -------
    float d4[2][4][4] = {};
    #pragma unroll
    for (int it = 0; it < 2; ++it) {
        int task = wid + 8 * it;              // 0..15
        int h = task >> 2, qt = task & 3;
        int row0 = qt * 16;

        // --- QK^T; accumulators pre-initialized with (bias+mask)*log2e from gBM ---
        const float2* bmh = gBM + ((size_t)(bx & 63) * 4 + h) * (7 * 64 * 4);
        float dq[7][4];
        #pragma unroll
        for (int jb = 0; jb < 7; ++jb) {
            float2 bmA = bmh[(jb * 64 + row0 + g) * 4 + t];       // row g
            float2 bmB = bmh[(jb * 64 + row0 + 8 + g) * 4 + t];   // row g+8
            dq[jb][0] = bmA.x;  dq[jb][1] = bmA.y;
            dq[jb][2] = bmB.x;  dq[jb][3] = bmB.y;
        }
        #pragma unroll
        for (int kb2 = 0; kb2 < 2; ++kb2) {
            int kb = 2 * h + kb2;
            unsigned ah[4], al[4];
            ldsm4(ah, xhh_b + row0 * 272 + kb * 32);
            ldsm4(al, xhl_b + row0 * 272 + kb * 32);
            int kw = kb * 8 + t;
            #pragma unroll
            for (int jb = 0; jb < 7; ++jb) {
                int kr = jb * 8 + g;
                mma3(dq[jb], ah, al, KH[kr * 68 + kw], KH[kr * 68 + kw + 4]);
            }
        }

        // --- softmax in log2 domain -> packed A fragments (regs) ---
        uint2 pa[7], pb[7];
        #pragma unroll
        for (int rr = 0; rr < 2; ++rr) {
            float mx = -INFINITY;
            #pragma unroll
            for (int jb = 0; jb < 7; ++jb)
                mx = fmaxf(mx, fmaxf(dq[jb][rr * 2], dq[jb][rr * 2 + 1]));
            mx = fmaxf(mx, __shfl_xor_sync(0xffffffffu, mx, 1));
            mx = fmaxf(mx, __shfl_xor_sync(0xffffffffu, mx, 2));
            float sv[14];
            float sum = 0.f;
            #pragma unroll
            for (int jb = 0; jb < 7; ++jb) {
                sv[2 * jb]     = ex2f(dq[jb][rr * 2]     - mx);
                sv[2 * jb + 1] = ex2f(dq[jb][rr * 2 + 1] - mx);
                sum += sv[2 * jb] + sv[2 * jb + 1];
            }
            sum += __shfl_xor_sync(0xffffffffu, sum, 1);
            sum += __shfl_xor_sync(0xffffffffu, sum, 2);
            float inv = 1.f / sum;
            uint2* dst = rr ? pb : pa;
            #pragma unroll
            for (int jb = 0; jb < 7; ++jb)
                dst[jb] = split_pack(sv[2 * jb] * inv, sv[2 * jb + 1] * inv);
        }

        // --- AV (A = packed probs from regs, B = VT) ---
        #pragma unroll
        for (int kb = 0; kb < 4; ++kb) {
            const int jb0 = 2 * kb, jb1 = 2 * kb + 1;
            unsigned ah[4], al[4];
            ah[0] = pa[jb0].x;  al[0] = pa[jb0].y;
            ah[1] = pb[jb0].x;  al[1] = pb[jb0].y;
            if (jb1 < 7) {
                ah[2] = pa[jb1].x;  al[2] = pa[jb1].y;
                ah[3] = pb[jb1].x;  al[3] = pb[jb1].y;
            } else {
                ah[2] = 0; al[2] = 0; ah[3] = 0; al[3] = 0;
            }
            int kw = kb * 8 + t;
            #pragma unroll
            for (int nb = 0; nb < 4; ++nb) {
                int c = 32 * h + nb * 8 + g;
                mma3(d4[it][nb], ah, al, VT[c * 36 + kw], VT[c * 36 + kw + 4]);
            }
        }
    }
    __syncthreads();                          // VT/KH/q reads done; OV planes writable

    #pragma unroll
    for (int it = 0; it < 2; ++it) {
        int task = wid + 8 * it;
        int h = task >> 2, qt = task & 3;
        int l0 = qt * 16 + g;
        #pragma unroll
        for (int nb = 0; nb < 4; ++nb) {
            int cw = 16 * h + nb * 4 + t;
            if (l0 < 49) {
                uint2 p = split_pack(d4[it][nb][0], d4[it][nb][1]);
                XHH[l0 * 68 + cw] = p.x;
                XHL[l0 * 68 + cw] = p.y;
            }
            if (l0 + 8 < 49) {
                uint2 p = split_pack(d4[it][nb][2], d4[it][nb][3]);
                XHH[(l0 + 8) * 68 + cw] = p.x;
                XHL[(l0 + 8) * 68 + cw] = p.y;
            }
        }
    }
    __syncthreads();

    // ---------------- phase 5: proj GEMM (col block 48), bias-folded init ----------------
    {
        float d[2][4][4];
        #pragma unroll
        for (int nb = 0; nb < 4; ++nb) {
            int c = cb + nb * 8 + 2 * t;
            float b0 = proj_b[c], b1 = proj_b[c + 1];
            #pragma unroll
            for (int sub = 0; sub < 2; ++sub) {
                d[sub][nb][0] = b0; d[sub][nb][1] = b1;
                d[sub][nb][2] = b0; d[sub][nb][3] = b1;
            }
        }
        mma_dense_ldsm(xhh_b + rbase * 272, xhl_b + rbase * 272, gBq + 48 * 256, d, lane);
        float* og = out + (size_t)bx * 49 * 128;
        #pragma unroll
        for (int sub = 0; sub < 2; ++sub) {
            int r0 = rbase + sub * 16 + g, r1 = r0 + 8;
            #pragma unroll
            for (int nb = 0; nb < 4; ++nb) {
                int c = cb + nb * 8 + 2 * t;
                if (r0 < 49)
                    *(float2*)(og + r0 * 128 + c) = make_float2(d[sub][nb][0], d[sub][nb][1]);
                if (r1 < 49)
                    *(float2*)(og + r1 * 128 + c) = make_float2(d[sub][nb][2], d[sub][nb][3]);
            }
        }
    }
}

extern "C" void kernel_launch(void* const* d_in, const int* in_sizes, int n_in,
                              void* d_out, int out_size)
{
    const float* x          = (const float*)d_in[0];
    const float* attn_mask  = (const float*)d_in[1];
    const float* qkv_w      = (const float*)d_in[2];
    const float* qkv_b      = (const float*)d_in[3];
    const float* proj_w     = (const float*)d_in[4];
    const float* proj_b     = (const float*)d_in[5];
    const float* bias_table = (const float*)d_in[6];
    const int*   rel_idx    = (const int*)d_in[7];
    float* out = (float*)d_out;

    const int bm_blocks = (64 * 4 * 7 * 64 * 4 + 255) / 256;   // 1792
    prep_all<<<64 + bm_blocks, 256>>>(qkv_w, proj_w, attn_mask, bias_table, rel_idx);

    const int smem_bytes = SM_U2 * 8;                          // 97,792 B -> 2 CTAs/SM
    cudaFuncSetAttribute(wmsa_fused_kernel,
                         cudaFuncAttributeMaxDynamicSharedMemorySize, smem_bytes);

    const int n_windows = in_sizes[0] / (49 * 128);            // 4096
    wmsa_fused_kernel<<<n_windows, NTHR, smem_bytes>>>(x, qkv_b, proj_b, out);
}

// round 17
// speedup vs baseline: 1.3256x; 1.0040x over previous
#include <cuda_runtime.h>

#define LOG2E 1.4426950408889634
#define S2    ((float)(0.17677669529663687 * LOG2E))   // qk scale folded with log2e
#define NTHR  256

// u32-word smem offsets — per-CTA smem = 97,792 B (2 CTAs/SM)
// XHH [0,3808)   : hi plane, 56 rows x 68 words (stride 272B, LDSM-clean)
// XHL [3808,7616): lo plane
// KH  [7616,15232): uint2 56x68 (hi,lo packed) — B operand for QK
// VT  [15232,24448): uint2 128x36 — B operand for AV
// OV planes overlay XH planes after attention
#define SM_U2 12224

__device__ uint4  gW4[64 * 8 * 8 * 4];       // fragment-major pre-split weights (Q cols pre-scaled by S2)
__device__ float2 gBM[64 * 4 * 7 * 64 * 4];  // (bias+mask)*log2e: [wm][h][jb][li(64)][t]

__device__ __forceinline__ unsigned pack_bf(float x0, float x1) {
    unsigned r;
    asm("cvt.rn.bf16x2.f32 %0, %1, %2;" : "=r"(r) : "f"(x1), "f"(x0));
    return r;
}
__device__ __forceinline__ uint2 split_pack(float x0, float x1) {
    unsigned h = pack_bf(x0, x1);
    float h0 = __uint_as_float(h << 16);
    float h1 = __uint_as_float(h & 0xffff0000u);
    unsigned l = pack_bf(x0 - h0, x1 - h1);
    return make_uint2(h, l);
}
__device__ __forceinline__ float ex2f(float x) {
    float r; asm("ex2.approx.ftz.f32 %0, %1;" : "=f"(r) : "f"(x)); return r;
}
__device__ __forceinline__ void mmabf(float* d, const unsigned* a, const unsigned* b) {
    asm volatile("mma.sync.aligned.m16n8k16.row.col.f32.bf16.bf16.f32 "
        "{%0,%1,%2,%3},{%4,%5,%6,%7},{%8,%9},{%0,%1,%2,%3};"
        : "+f"(d[0]), "+f"(d[1]), "+f"(d[2]), "+f"(d[3])
        : "r"(a[0]), "r"(a[1]), "r"(a[2]), "r"(a[3]), "r"(b[0]), "r"(b[1]));
}
__device__ __forceinline__ void mma3(float* d, const unsigned ah[4], const unsigned al[4],
                                     uint2 b0, uint2 b1) {
    unsigned bh[2] = {b0.x, b1.x};
    unsigned bl[2] = {b0.y, b1.y};
    mmabf(d, ah, bl);
    mmabf(d, al, bh);
    mmabf(d, ah, bh);
}
__device__ __forceinline__ void ldsm4(unsigned r[4], unsigned a) {
    asm volatile("ldmatrix.sync.aligned.m8n8.x4.shared.b16 {%0,%1,%2,%3}, [%4];"
        : "=r"(r[0]), "=r"(r[1]), "=r"(r[2]), "=r"(r[3]) : "r"(a));
}

// Dense stage: warp computes 32 rows (two 16-row subtiles) x 32 cols, K=128.
// B fragments explicitly double-buffered in registers: LDG(kb+1) issues before mma(kb),
// hiding L2 latency behind the mma block. d pre-initialized (bias-fold) by caller.
__device__ __forceinline__ void mma_dense_ldsm(unsigned hb, unsigned lb,
                                               const uint4* __restrict__ gBw,
                                               float d[2][4][4], int lane)
{
    uint4 fcur[4];
    #pragma unroll
    for (int nb = 0; nb < 4; ++nb)
        fcur[nb] = gBw[nb * 256 + lane];
    #pragma unroll
    for (int kb = 0; kb < 8; ++kb) {
        uint4 fnext[4];
        if (kb < 7) {
            #pragma unroll
            for (int nb = 0; nb < 4; ++nb)
                fnext[nb] = gBw[nb * 256 + (kb + 1) * 32 + lane];
        }
        unsigned ah0[4], al0[4], ah1[4], al1[4];
        ldsm4(ah0, hb + kb * 32);
        ldsm4(al0, lb + kb * 32);
        ldsm4(ah1, hb + 4352 + kb * 32);     // +16 rows * 272B
        ldsm4(al1, lb + 4352 + kb * 32);
        #pragma unroll
        for (int nb = 0; nb < 4; ++nb) {
            uint2 b0 = make_uint2(fcur[nb].x, fcur[nb].y);
            uint2 b1 = make_uint2(fcur[nb].z, fcur[nb].w);
            mma3(d[0][nb], ah0, al0, b0, b1);
            mma3(d[1][nb], ah1, al1, b0, b1);
        }
        if (kb < 7) {
            #pragma unroll
            for (int nb = 0; nb < 4; ++nb)
                fcur[nb] = fnext[nb];
        }
    }
}

// combined prep: blocks [0,64) build gW4, blocks [64,..) build gBM
__global__ void prep_all(const float* __restrict__ qkv_w,
                         const float* __restrict__ proj_w,
                         const float* __restrict__ attn_mask,
                         const float* __restrict__ bias_table,
                         const int*   __restrict__ rel_idx)
{
    if (blockIdx.x < 64) {
        int idx = blockIdx.x * 256 + threadIdx.x;       // 0..16383
        int t    = idx & 3;
        int g    = (idx >> 2) & 7;
        int kb   = (idx >> 5) & 7;
        int cblk = idx >> 8;
        int col  = cblk * 8 + g;
        const float* src = (col < 384) ? (qkv_w + (size_t)col * 128)
                                       : (proj_w + (size_t)(col - 384) * 128);
        float s = (col < 128) ? S2 : 1.0f;              // fold qk-scale*log2e into Q weights
        int w0 = kb * 8 + t, w1 = w0 + 4;
        uint2 p0 = split_pack(src[2 * w0] * s, src[2 * w0 + 1] * s);
        uint2 p1 = split_pack(src[2 * w1] * s, src[2 * w1 + 1] * s);
        gW4[idx] = make_uint4(p0.x, p0.y, p1.x, p1.y);
    } else {
        int idx = (blockIdx.x - 64) * 256 + threadIdx.x;
        if (idx >= 64 * 4 * 7 * 64 * 4) return;
        int t  = idx & 3;
        int q  = idx >> 2;
        int li = q & 63;   q >>= 6;
        int jb = q % 7;    q /= 7;
        int h  = q & 3;
        int wm = q >> 2;
        int j0 = jb * 8 + 2 * t;
        float v0 = -1e30f, v1 = -1e30f;
        if (li < 49 && j0 < 49)
            v0 = (bias_table[rel_idx[li * 49 + j0] * 4 + h]
                  + attn_mask[wm * 2401 + li * 49 + j0]) * (float)LOG2E;
        if (li < 49 && j0 + 1 < 49)
            v1 = (bias_table[rel_idx[li * 49 + j0 + 1] * 4 + h]
                  + attn_mask[wm * 2401 + li * 49 + j0 + 1]) * (float)LOG2E;
        gBM[idx] = make_float2(v0, v1);
    }
}

__global__ __launch_bounds__(NTHR, 2)
void wmsa_fused_kernel(const float* __restrict__ x,
                       const float* __restrict__ qkv_b,
                       const float* __restrict__ proj_b,
                       float* __restrict__ out)
{
    extern __shared__ unsigned sm32[];
    unsigned* XHH = sm32;                    // hi plane (x -> q -> ov)
    unsigned* XHL = sm32 + 3808;             // lo plane
    uint2*    KH  = (uint2*)(sm32 + 7616);
    uint2*    VT  = (uint2*)(sm32 + 15232);

    const int tid  = threadIdx.x;
    const int bx   = blockIdx.x;
    const int lane = tid & 31;
    const int wid  = tid >> 5;               // 0..7
    const int g    = lane >> 2;
    const int t    = lane & 3;

    const int mt2   = wid >> 2;              // 0..1
    const int nh    = wid & 3;
    const int rbase = mt2 * 32;
    const int cb    = nh * 32;
    const uint4* gBq = gW4 + (cb >> 3) * 256;

    const unsigned sb = (unsigned)__cvta_generic_to_shared(sm32);
    const unsigned rowoff = (lane & 15) * 272 + (lane >> 4) * 16;  // canonical LDSM addr
    const unsigned xhh_b = sb + rowoff;
    const unsigned xhl_b = sb + 3808u * 4 + rowoff;

    // ---------------- phase 0: load+split x (planes) ; zero VT + KH pads ----------------
    {
        const float2* xg = (const float2*)(x + (size_t)bx * 49 * 128);
        for (int idx = tid; idx < 49 * 64; idx += NTHR) {
            float2 v = xg[idx];
            uint2 p = split_pack(v.x, v.y);
            int o = (idx >> 6) * 68 + (idx & 63);
            XHH[o] = p.x;
            XHL[o] = p.y;
        }
        for (int idx = tid; idx < 128 * 36; idx += NTHR)
            VT[idx] = make_uint2(0, 0);
        for (int idx = tid; idx < 7 * 68; idx += NTHR)      // KH rows 49..55 = 0
            KH[49 * 68 + idx] = make_uint2(0, 0);
    }
    __syncthreads();

    // ---------------- phase 1: K, V, Q (bias pre-folded into accumulator init) ----------------
    {   // K (col block 16)
        float d[2][4][4];
        #pragma unroll
        for (int nb = 0; nb < 4; ++nb) {
            int c = cb + nb * 8 + 2 * t;
            float b0 = qkv_b[128 + c], b1 = qkv_b[129 + c];
            #pragma unroll
            for (int sub = 0; sub < 2; ++sub) {
                d[sub][nb][0] = b0; d[sub][nb][1] = b1;
                d[sub][nb][2] = b0; d[sub][nb][3] = b1;
            }
        }
        mma_dense_ldsm(xhh_b + rbase * 272, xhl_b + rbase * 272, gBq + 16 * 256, d, lane);
        #pragma unroll
        for (int sub = 0; sub < 2; ++sub) {
            int r0 = rbase + sub * 16 + g, r1 = r0 + 8;
            #pragma unroll
            for (int nb = 0; nb < 4; ++nb) {
                int wcol = (cb + nb * 8 + 2 * t) >> 1;
                if (r0 < 49) KH[r0 * 68 + wcol] = split_pack(d[sub][nb][0], d[sub][nb][1]);
                if (r1 < 49) KH[r1 * 68 + wcol] = split_pack(d[sub][nb][2], d[sub][nb][3]);
            }
        }
    }
    {   // V (col block 32) -> VT transposed via shfl pairing
        float d[2][4][4];
        #pragma unroll
        for (int nb = 0; nb < 4; ++nb) {
            int c = cb + nb * 8 + 2 * t;
            float b0 = qkv_b[256 + c], b1 = qkv_b[257 + c];
            #pragma unroll
            for (int sub = 0; sub < 2; ++sub) {
                d[sub][nb][0] = b0; d[sub][nb][1] = b1;
                d[sub][nb][2] = b0; d[sub][nb][3] = b1;
            }
        }
        mma_dense_ldsm(xhh_b + rbase * 272, xhl_b + rbase * 272, gBq + 32 * 256, d, lane);
        #pragma unroll
        for (int sub = 0; sub < 2; ++sub) {
            #pragma unroll
            for (int nb = 0; nb < 4; ++nb) {
                int c = cb + nb * 8 + 2 * t;
                #pragma unroll
                for (int rr = 0; rr < 2; ++rr) {
                    float vc  = d[sub][nb][2 * rr];
                    float vc1 = d[sub][nb][2 * rr + 1];
                    float oc  = __shfl_xor_sync(0xffffffffu, vc, 4);
                    float oc1 = __shfl_xor_sync(0xffffffffu, vc1, 4);
                    int il = rbase + sub * 16 + rr * 8 + g;
                    if (!(g & 1) && il < 49) {
                        float e1 = (il + 1 < 49) ? oc  : 0.f;
                        float f1 = (il + 1 < 49) ? oc1 : 0.f;
                        int u = il >> 1;
                        VT[c * 36 + u]       = split_pack(vc,  e1);
                        VT[(c + 1) * 36 + u] = split_pack(vc1, f1);
                    }
                }
            }
        }
    }
    {   // Q (col block 0, weights pre-scaled by S2): compute, sync, overwrite XH planes
        float d[2][4][4];
        #pragma unroll
        for (int nb = 0; nb < 4; ++nb) {
            int c = cb + nb * 8 + 2 * t;
            float b0 = qkv_b[c] * S2, b1 = qkv_b[c + 1] * S2;
            #pragma unroll
            for (int sub = 0; sub < 2; ++sub) {
                d[sub][nb][0] = b0; d[sub][nb][1] = b1;
                d[sub][nb][2] = b0; d[sub][nb][3] = b1;
            }
        }
        mma_dense_ldsm(xhh_b + rbase * 272, xhl_b + rbase * 272, gBq, d, lane);
        __syncthreads();                      // all XH reads done
        #pragma unroll
        for (int sub = 0; sub < 2; ++sub) {
            int r0 = rbase + sub * 16 + g, r1 = r0 + 8;
            #pragma unroll
            for (int nb = 0; nb < 4; ++nb) {
                int wcol = (cb + nb * 8 + 2 * t) >> 1;
                if (r0 < 49) {
                    uint2 p = split_pack(d[sub][nb][0], d[sub][nb][1]);
                    XHH[r0 * 68 + wcol] = p.x;
                    XHL[r0 * 68 + wcol] = p.y;
                }
                if (r1 < 49) {
                    uint2 p = split_pack(d[sub][nb][2], d[sub][nb][3]);
                    XHH[r1 * 68 + wcol] = p.x;
                    XHL[r1 * 68 + wcol] = p.y;
                }
            }
        }
    }
    __syncthreads();

    // ------- phases 2-4 fused: per-task QK(init=bias+mask) -> exp2 softmax -> AV -------
    float d4[2][4][4] = {};
    #pragma unroll
    for (int it = 0; it < 2; ++it) {
        int task = wid + 8 * it;              // 0..15
        int h = task >> 2, qt = task & 3;
        int row0 = qt * 16;

        // --- QK^T; accumulators pre-initialized with (bias+mask)*log2e from gBM ---
        const float2* bmh = gBM + ((size_t)(bx & 63) * 4 + h) * (7 * 64 * 4);
        float dq[7][4];
        #pragma unroll
        for (int jb = 0; jb < 7; ++jb) {
            float2 bmA = bmh[(jb * 64 + row0 + g) * 4 + t];       // row g
            float2 bmB = bmh[(jb * 64 + row0 + 8 + g) * 4 + t];   // row g+8
            dq[jb][0] = bmA.x;  dq[jb][1] = bmA.y;
            dq[jb][2] = bmB.x;  dq[jb][3] = bmB.y;
        }
        #pragma unroll
        for (int kb2 = 0; kb2 < 2; ++kb2) {
            int kb = 2 * h + kb2;
            unsigned ah[4], al[4];
            ldsm4(ah, xhh_b + row0 * 272 + kb * 32);
            ldsm4(al, xhl_b + row0 * 272 + kb * 32);
            int kw = kb * 8 + t;
            #pragma unroll
            for (int jb = 0; jb < 7; ++jb) {
                int kr = jb * 8 + g;
                mma3(dq[jb], ah, al, KH[kr * 68 + kw], KH[kr * 68 + kw + 4]);
            }
        }

        // --- softmax in log2 domain -> packed A fragments (regs) ---
        uint2 pa[7], pb[7];
        #pragma unroll
        for (int rr = 0; rr < 2; ++rr) {
            float mx = -INFINITY;
            #pragma unroll
            for (int jb = 0; jb < 7; ++jb)
                mx = fmaxf(mx, fmaxf(dq[jb][rr * 2], dq[jb][rr * 2 + 1]));
            mx = fmaxf(mx, __shfl_xor_sync(0xffffffffu, mx, 1));
            mx = fmaxf(mx, __shfl_xor_sync(0xffffffffu, mx, 2));
            float sv[14];
            float sum = 0.f;
            #pragma unroll
            for (int jb = 0; jb < 7; ++jb) {
                sv[2 * jb]     = ex2f(dq[jb][rr * 2]     - mx);
                sv[2 * jb + 1] = ex2f(dq[jb][rr * 2 + 1] - mx);
                sum += sv[2 * jb] + sv[2 * jb + 1];
            }
            sum += __shfl_xor_sync(0xffffffffu, sum, 1);
            sum += __shfl_xor_sync(0xffffffffu, sum, 2);
            float inv = 1.f / sum;
            uint2* dst = rr ? pb : pa;
            #pragma unroll
            for (int jb = 0; jb < 7; ++jb)
                dst[jb] = split_pack(sv[2 * jb] * inv, sv[2 * jb + 1] * inv);
        }

        // --- AV (A = packed probs from regs, B = VT) ---
        #pragma unroll
        for (int kb = 0; kb < 4; ++kb) {
            const int jb0 = 2 * kb, jb1 = 2 * kb + 1;
            unsigned ah[4], al[4];
            ah[0] = pa[jb0].x;  al[0] = pa[jb0].y;
            ah[1] = pb[jb0].x;  al[1] = pb[jb0].y;
            if (jb1 < 7) {
                ah[2] = pa[jb1].x;  al[2] = pa[jb1].y;
                ah[3] = pb[jb1].x;  al[3] = pb[jb1].y;
            } else {
                ah[2] = 0; al[2] = 0; ah[3] = 0; al[3] = 0;
            }
            int kw = kb * 8 + t;
            #pragma unroll
            for (int nb = 0; nb < 4; ++nb) {
                int c = 32 * h + nb * 8 + g;
                mma3(d4[it][nb], ah, al, VT[c * 36 + kw], VT[c * 36 + kw + 4]);
            }
        }
    }
    __syncthreads();                          // VT/KH/q reads done; OV planes writable

    #pragma unroll
    for (int it = 0; it < 2; ++it) {
        int task = wid + 8 * it;
        int h = task >> 2, qt = task & 3;
        int l0 = qt * 16 + g;
        #pragma unroll
        for (int nb = 0; nb < 4; ++nb) {
            int cw = 16 * h + nb * 4 + t;
            if (l0 < 49) {
                uint2 p = split_pack(d4[it][nb][0], d4[it][nb][1]);
                XHH[l0 * 68 + cw] = p.x;
                XHL[l0 * 68 + cw] = p.y;
            }
            if (l0 + 8 < 49) {
                uint2 p = split_pack(d4[it][nb][2], d4[it][nb][3]);
                XHH[(l0 + 8) * 68 + cw] = p.x;
                XHL[(l0 + 8) * 68 + cw] = p.y;
            }
        }
    }
    __syncthreads();

    // ---------------- phase 5: proj GEMM (col block 48), bias-folded init ----------------
    {
        float d[2][4][4];
        #pragma unroll
        for (int nb = 0; nb < 4; ++nb) {
            int c = cb + nb * 8 + 2 * t;
            float b0 = proj_b[c], b1 = proj_b[c + 1];
            #pragma unroll
            for (int sub = 0; sub < 2; ++sub) {
                d[sub][nb][0] = b0; d[sub][nb][1] = b1;
                d[sub][nb][2] = b0; d[sub][nb][3] = b1;
            }
        }
        mma_dense_ldsm(xhh_b + rbase * 272, xhl_b + rbase * 272, gBq + 48 * 256, d, lane);
        float* og = out + (size_t)bx * 49 * 128;
        #pragma unroll
        for (int sub = 0; sub < 2; ++sub) {
            int r0 = rbase + sub * 16 + g, r1 = r0 + 8;
            #pragma unroll
            for (int nb = 0; nb < 4; ++nb) {
                int c = cb + nb * 8 + 2 * t;
                if (r0 < 49)
                    *(float2*)(og + r0 * 128 + c) = make_float2(d[sub][nb][0], d[sub][nb][1]);
                if (r1 < 49)
                    *(float2*)(og + r1 * 128 + c) = make_float2(d[sub][nb][2], d[sub][nb][3]);
            }
        }
    }
}

extern "C" void kernel_launch(void* const* d_in, const int* in_sizes, int n_in,
                              void* d_out, int out_size)
{
    const float* x          = (const float*)d_in[0];
    const float* attn_mask  = (const float*)d_in[1];
    const float* qkv_w      = (const float*)d_in[2];
    const float* qkv_b      = (const float*)d_in[3];
    const float* proj_w     = (const float*)d_in[4];
    const float* proj_b     = (const float*)d_in[5];
    const float* bias_table = (const float*)d_in[6];
    const int*   rel_idx    = (const int*)d_in[7];
    float* out = (float*)d_out;

    const int bm_blocks = (64 * 4 * 7 * 64 * 4 + 255) / 256;   // 1792
    prep_all<<<64 + bm_blocks, 256>>>(qkv_w, proj_w, attn_mask, bias_table, rel_idx);

    const int smem_bytes = SM_U2 * 8;                          // 97,792 B -> 2 CTAs/SM
    cudaFuncSetAttribute(wmsa_fused_kernel,
                         cudaFuncAttributeMaxDynamicSharedMemorySize, smem_bytes);

    const int n_windows = in_sizes[0] / (49 * 128);            // 4096
    wmsa_fused_kernel<<<n_windows, NTHR, smem_bytes>>>(x, qkv_b, proj_b, out);
}